// round 10
// baseline (speedup 1.0000x reference)
#include <cuda_runtime.h>
#include <cuda_fp16.h>
#include <math.h>
#include <stdint.h>

#define BATCH 2
#define SEQ   4096
#define EMBED 768
#define NHEAD 8
#define HDIM  96
#define MTOT  (BATCH*SEQ)          // 8192
#define QKV_N (3*EMBED)            // 2304
#define C2EXP  0.14724446f         // 96^-0.5 * log2(e)

// ------------------------- device scratch (fp16) -------------------------
__device__ __align__(16) __half g_q[(size_t)BATCH*NHEAD*SEQ*HDIM];   // [B,H,N,D]
__device__ __align__(16) __half g_k[(size_t)BATCH*NHEAD*SEQ*HDIM];   // [B,H,N,D]
__device__ __align__(16) __half g_v[(size_t)BATCH*NHEAD*SEQ*HDIM];   // [B,H,D,N]
__device__ __align__(16) __half g_xh[(size_t)MTOT*EMBED];
__device__ __align__(16) __half g_wqkvh[(size_t)QKV_N*EMBED];
__device__ __align__(16) __half g_wprojh[(size_t)EMBED*EMBED];
__device__ __align__(16) __half g_atth[(size_t)MTOT*EMBED];

// ------------------------- helpers -------------------------
__device__ __forceinline__ void mma16(float* c, uint32_t a0, uint32_t a1,
                                      uint32_t a2, uint32_t a3,
                                      uint32_t b0, uint32_t b1) {
    asm volatile(
        "mma.sync.aligned.m16n8k16.row.col.f32.f16.f16.f32 "
        "{%0,%1,%2,%3}, {%4,%5,%6,%7}, {%8,%9}, {%0,%1,%2,%3};"
        : "+f"(c[0]), "+f"(c[1]), "+f"(c[2]), "+f"(c[3])
        : "r"(a0), "r"(a1), "r"(a2), "r"(a3), "r"(b0), "r"(b1));
}

#define LDSM4(R, addr) \
    asm volatile("ldmatrix.sync.aligned.m8n8.x4.shared.b16 {%0,%1,%2,%3}, [%4];" \
        : "=r"((R)[0]), "=r"((R)[1]), "=r"((R)[2]), "=r"((R)[3]) : "r"(addr))

__device__ __forceinline__ void cpasync16(uint32_t dst, const void* src) {
    asm volatile("cp.async.cg.shared.global [%0], [%1], 16;\n"
                 :: "r"(dst), "l"(src));
}

__device__ __forceinline__ uint32_t s2u(const void* p) {
    uint32_t a;
    asm("{ .reg .u64 t; cvta.to.shared.u64 t, %1; cvt.u32.u64 %0, t; }"
        : "=r"(a) : "l"(p));
    return a;
}

__device__ __forceinline__ uint32_t h2u(__half2 h) {
    return *(uint32_t*)&h;
}

// ------------------------- fp32 -> fp16 convert -------------------------
__global__ void cvt_half(const float* __restrict__ s, __half* __restrict__ d, int n2) {
    for (int i = blockIdx.x * blockDim.x + threadIdx.x; i < n2;
         i += gridDim.x * blockDim.x) {
        float2 v = ((const float2*)s)[i];
        ((__half2*)d)[i] = __floats2half2_rn(v.x, v.y);
    }
}

// ---------------------------------------------------------------------------
// fp16 GEMM: C = A @ B^T, m16n8k16, f32 accum, ldmatrix fragment loads.
// 128x128 CTA tile, BK=64, cp.async 2-stage, 8 warps of 64x32, 2 CTAs/SM.
// ---------------------------------------------------------------------------
#define HGP 72
#define HST (128*HGP*2)
#define HGEMM_SMEM (4*HST)

template<int MODE>
__global__ __launch_bounds__(256, 2) void hgemm(float* __restrict__ Cout) {
    extern __shared__ char dynsm[];
    const uint32_t sb = s2u(dynsm);
    const int t = threadIdx.x, w = t >> 5, l = t & 31, g = l >> 2, q = l & 3;
    const int wm = (w >> 2) * 64, wn = (w & 3) * 32;
    const int m0 = blockIdx.y * 128, n0 = blockIdx.x * 128;
    const int K = EMBED;

    // ldmatrix lane geometry
    const int arow = (l & 7) + 8 * ((l >> 3) & 1);   // A: row offset in 16
    const int acol = 8 * (l >> 4);                   // A: col offset in 16
    const int brow = (l & 7) + 8 * (l >> 4);         // B: row offset in 16 (ni pair)
    const int bcol = 8 * ((l >> 3) & 1);             // B: col offset in 16

    const __half* A = (MODE == 0) ? g_xh : g_atth;
    const __half* B = (MODE == 0) ? g_wqkvh : g_wprojh;

    auto load_chunk = [&](int s, int kt) {
        uint32_t base = sb + s * (2 * HST);
#pragma unroll
        for (int j = 0; j < 8; j++) {
            int idx = t + j * 256;
            int tile = idx >> 10, rem = idx & 1023;
            int r = rem >> 3, cb = rem & 7;
            const __half* src = tile ? (B + (size_t)(n0 + r) * K)
                                     : (A + (size_t)(m0 + r) * K);
            cpasync16(base + tile * HST + (uint32_t)((r * HGP + cb * 8) * 2),
                      src + kt + cb * 8);
        }
        asm volatile("cp.async.commit_group;\n" ::);
    };

    float acc[4][4][4];
#pragma unroll
    for (int mi = 0; mi < 4; mi++)
#pragma unroll
        for (int ni = 0; ni < 4; ni++)
#pragma unroll
            for (int c = 0; c < 4; c++) acc[mi][ni][c] = 0.f;

    load_chunk(0, 0);

    for (int c = 0; c < 12; c++) {
        if (c + 1 < 12) {
            load_chunk((c + 1) & 1, (c + 1) * 64);
            asm volatile("cp.async.wait_group 1;\n" ::);
        } else {
            asm volatile("cp.async.wait_group 0;\n" ::);
        }
        __syncthreads();

        uint32_t as_s = sb + (c & 1) * (2 * HST);
        uint32_t bs_s = as_s + HST;

#pragma unroll
        for (int ks = 0; ks < 4; ks++) {
            uint32_t af[4][4], bf[4][4];
#pragma unroll
            for (int mi = 0; mi < 4; mi++)
                LDSM4(af[mi], as_s + (uint32_t)(((wm + 16*mi + arow) * HGP
                                                + 16*ks + acol) * 2));
#pragma unroll
            for (int p = 0; p < 2; p++)
                LDSM4(bf[p], bs_s + (uint32_t)(((wn + 16*p + brow) * HGP
                                                + 16*ks + bcol) * 2));
#pragma unroll
            for (int mi = 0; mi < 4; mi++)
#pragma unroll
                for (int ni = 0; ni < 4; ni++)
                    mma16(acc[mi][ni], af[mi][0], af[mi][1], af[mi][2], af[mi][3],
                          bf[ni >> 1][(ni & 1) * 2], bf[ni >> 1][(ni & 1) * 2 + 1]);
        }
        __syncthreads();
    }

#pragma unroll
    for (int mi = 0; mi < 4; mi++) {
        int gr0 = m0 + wm + 16 * mi + g;
        int gr1 = gr0 + 8;
#pragma unroll
        for (int ni = 0; ni < 4; ni++) {
            int colb = n0 + wn + 8 * ni;
            if (MODE == 0) {
                int which = colb / EMBED;
                int rem = colb - which * EMBED;
                int h = rem / HDIM;
                int d0 = rem - h * HDIM + 2 * q;
                int b0i = gr0 >> 12, n0i = gr0 & 4095;
                int b1i = gr1 >> 12, n1i = gr1 & 4095;
                if (which < 2) {
                    __half* dst = which ? g_k : g_q;
                    size_t i0 = (((size_t)(b0i * NHEAD + h)) * SEQ + n0i) * HDIM + d0;
                    size_t i1 = (((size_t)(b1i * NHEAD + h)) * SEQ + n1i) * HDIM + d0;
                    *(__half2*)(dst + i0) = __floats2half2_rn(acc[mi][ni][0], acc[mi][ni][1]);
                    *(__half2*)(dst + i1) = __floats2half2_rn(acc[mi][ni][2], acc[mi][ni][3]);
                } else {
                    size_t base0 = (((size_t)(b0i * NHEAD + h)) * HDIM + d0) * SEQ;
                    size_t base1 = (((size_t)(b1i * NHEAD + h)) * HDIM + d0) * SEQ;
                    g_v[base0 + n0i]       = __float2half(acc[mi][ni][0]);
                    g_v[base0 + SEQ + n0i] = __float2half(acc[mi][ni][1]);
                    g_v[base1 + n1i]       = __float2half(acc[mi][ni][2]);
                    g_v[base1 + SEQ + n1i] = __float2half(acc[mi][ni][3]);
                }
            } else {
                size_t i0 = (size_t)gr0 * EMBED + colb + 2 * q;
                size_t i1 = (size_t)gr1 * EMBED + colb + 2 * q;
                *(float2*)(Cout + i0) = make_float2(acc[mi][ni][0], acc[mi][ni][1]);
                *(float2*)(Cout + i1) = make_float2(acc[mi][ni][2], acc[mi][ni][3]);
            }
        }
    }
}

// ---------------------------------------------------------------------------
// Flash attention, fp16 m16n8k16, ldmatrix fragments. Grid (SEQ/256, B*H),
// 256 threads, 1 CTA/SM. BM=256, BN=64, 8 warps x 32 rows.
// ---------------------------------------------------------------------------
#define FQP 104
#define FKP 104
#define FVP 72

__global__ __launch_bounds__(256, 1) void flash_h() {
    extern __shared__ char dynsm[];
    __half* Qs = (__half*)dynsm;                 // 256*FQP
    __half* Kb = Qs + 256*FQP;                   // 2 * 64*FKP
    __half* Vb = Kb + 2*64*FKP;                  // 2 * 96*FVP

    const int t = threadIdx.x;
    const int w = t >> 5, l = t & 31, g = l >> 2, q = l & 3;
    const int wm = w * 32;
    const int bh = blockIdx.y;
    const int q0 = blockIdx.x * 256;

    const int arow = (l & 7) + 8 * ((l >> 3) & 1);
    const int acol = 8 * (l >> 4);
    const int brow = (l & 7) + 8 * (l >> 4);
    const int bcol = 8 * ((l >> 3) & 1);

    const __half* Qg = g_q + (size_t)bh * SEQ * HDIM;
    const __half* Kg = g_k + (size_t)bh * SEQ * HDIM;
    const __half* Vg = g_v + (size_t)bh * HDIM * SEQ;   // [D,N]

    const uint32_t qs_s = s2u(Qs);
    const uint32_t kb_s = s2u(Kb);
    const uint32_t vb_s = s2u(Vb);

#pragma unroll
    for (int j = 0; j < 12; j++) {
        int idx = t + j * 256;
        int r = idx / 12, cb = idx % 12;
        cpasync16(qs_s + (uint32_t)((r * FQP + cb * 8) * 2),
                  Qg + (size_t)(q0 + r) * HDIM + cb * 8);
    }
    asm volatile("cp.async.commit_group;\n" ::);

    auto load_tile = [&](int s, int kt) {
#pragma unroll
        for (int j = 0; j < 3; j++) {
            int idx = t + j * 256;
            int r = idx / 12, cb = idx % 12;
            cpasync16(kb_s + (uint32_t)((s * 64 * FKP + r * FKP + cb * 8) * 2),
                      Kg + (size_t)(kt + r) * HDIM + cb * 8);
        }
#pragma unroll
        for (int j = 0; j < 3; j++) {
            int idx = t + j * 256;
            int r = idx >> 3, cb = idx & 7;
            cpasync16(vb_s + (uint32_t)((s * 96 * FVP + r * FVP + cb * 8) * 2),
                      Vg + (size_t)r * SEQ + kt + cb * 8);
        }
        asm volatile("cp.async.commit_group;\n" ::);
    };

    load_tile(0, 0);

    float of[2][12][4];
#pragma unroll
    for (int mi = 0; mi < 2; mi++)
#pragma unroll
        for (int ni = 0; ni < 12; ni++)
#pragma unroll
            for (int c = 0; c < 4; c++) of[mi][ni][c] = 0.f;
    float mrow[4] = {-INFINITY, -INFINITY, -INFINITY, -INFINITY};
    float lrow[4] = {0.f, 0.f, 0.f, 0.f};

    for (int it = 0; it < SEQ/64; it++) {
        asm volatile("cp.async.wait_group 0;\n" ::);
        __syncthreads();
        if (it + 1 < SEQ/64) load_tile((it + 1) & 1, (it + 1) * 64);

        const uint32_t kc_s = kb_s + (it & 1) * 64*FKP*2;
        const uint32_t vc_s = vb_s + (it & 1) * 96*FVP*2;

        // ---- S = Q K^T : warp tile 32 x 64, 6 k16-steps ----
        float sacc[2][8][4];
#pragma unroll
        for (int mi = 0; mi < 2; mi++)
#pragma unroll
            for (int ni = 0; ni < 8; ni++)
#pragma unroll
                for (int c = 0; c < 4; c++) sacc[mi][ni][c] = 0.f;

#pragma unroll
        for (int kk = 0; kk < 6; kk++) {
            uint32_t qf[2][4];
#pragma unroll
            for (int mi = 0; mi < 2; mi++)
                LDSM4(qf[mi], qs_s + (uint32_t)(((wm + 16*mi + arow) * FQP
                                                 + 16*kk + acol) * 2));
#pragma unroll
            for (int p = 0; p < 4; p++) {
                uint32_t bf[4];
                LDSM4(bf, kc_s + (uint32_t)(((16*p + brow) * FKP
                                             + 16*kk + bcol) * 2));
                mma16(sacc[0][2*p],   qf[0][0], qf[0][1], qf[0][2], qf[0][3], bf[0], bf[1]);
                mma16(sacc[0][2*p+1], qf[0][0], qf[0][1], qf[0][2], qf[0][3], bf[2], bf[3]);
                mma16(sacc[1][2*p],   qf[1][0], qf[1][1], qf[1][2], qf[1][3], bf[0], bf[1]);
                mma16(sacc[1][2*p+1], qf[1][0], qf[1][1], qf[1][2], qf[1][3], bf[2], bf[3]);
            }
        }

        // ---- register online softmax ----
        float tm[4] = {-INFINITY, -INFINITY, -INFINITY, -INFINITY};
#pragma unroll
        for (int mi = 0; mi < 2; mi++)
#pragma unroll
            for (int ni = 0; ni < 8; ni++) {
                tm[2*mi]   = fmaxf(tm[2*mi],   fmaxf(sacc[mi][ni][0], sacc[mi][ni][1]));
                tm[2*mi+1] = fmaxf(tm[2*mi+1], fmaxf(sacc[mi][ni][2], sacc[mi][ni][3]));
            }
        float sc[4], base[4], ssum[4];
#pragma unroll
        for (int r = 0; r < 4; r++) {
            tm[r] = fmaxf(tm[r], __shfl_xor_sync(0xffffffffu, tm[r], 1));
            tm[r] = fmaxf(tm[r], __shfl_xor_sync(0xffffffffu, tm[r], 2));
            float mn = fmaxf(mrow[r], tm[r]);
            sc[r]   = exp2f((mrow[r] - mn) * C2EXP);
            base[r] = mn * C2EXP;
            mrow[r] = mn;
            ssum[r] = 0.f;
        }
#pragma unroll
        for (int mi = 0; mi < 2; mi++)
#pragma unroll
            for (int ni = 0; ni < 8; ni++) {
                float p0 = exp2f(fmaf(sacc[mi][ni][0], C2EXP, -base[2*mi]));
                float p1 = exp2f(fmaf(sacc[mi][ni][1], C2EXP, -base[2*mi]));
                float p2 = exp2f(fmaf(sacc[mi][ni][2], C2EXP, -base[2*mi+1]));
                float p3 = exp2f(fmaf(sacc[mi][ni][3], C2EXP, -base[2*mi+1]));
                sacc[mi][ni][0] = p0; sacc[mi][ni][1] = p1;
                sacc[mi][ni][2] = p2; sacc[mi][ni][3] = p3;
                ssum[2*mi]   += p0 + p1;
                ssum[2*mi+1] += p2 + p3;
            }
#pragma unroll
        for (int r = 0; r < 4; r++) {
            ssum[r] += __shfl_xor_sync(0xffffffffu, ssum[r], 1);
            ssum[r] += __shfl_xor_sync(0xffffffffu, ssum[r], 2);
            lrow[r] = lrow[r] * sc[r] + ssum[r];
        }
        // skip O-rescale when no row in this warp saw a new max
        bool any_scale = !__all_sync(0xffffffffu,
            (sc[0] == 1.f) & (sc[1] == 1.f) & (sc[2] == 1.f) & (sc[3] == 1.f));
        if (any_scale) {
#pragma unroll
            for (int mi = 0; mi < 2; mi++)
#pragma unroll
                for (int ni = 0; ni < 12; ni++) {
                    of[mi][ni][0] *= sc[2*mi];   of[mi][ni][1] *= sc[2*mi];
                    of[mi][ni][2] *= sc[2*mi+1]; of[mi][ni][3] *= sc[2*mi+1];
                }
        }

        // ---- O += P @ V : C-layout == A-layout, register pack ----
#pragma unroll
        for (int kk2 = 0; kk2 < 4; kk2++) {
            uint32_t af[2][4];
#pragma unroll
            for (int mi = 0; mi < 2; mi++) {
                af[mi][0] = h2u(__floats2half2_rn(sacc[mi][2*kk2][0],   sacc[mi][2*kk2][1]));
                af[mi][1] = h2u(__floats2half2_rn(sacc[mi][2*kk2][2],   sacc[mi][2*kk2][3]));
                af[mi][2] = h2u(__floats2half2_rn(sacc[mi][2*kk2+1][0], sacc[mi][2*kk2+1][1]));
                af[mi][3] = h2u(__floats2half2_rn(sacc[mi][2*kk2+1][2], sacc[mi][2*kk2+1][3]));
            }
#pragma unroll
            for (int p = 0; p < 6; p++) {
                uint32_t bf[4];
                LDSM4(bf, vc_s + (uint32_t)(((16*p + brow) * FVP
                                             + 16*kk2 + bcol) * 2));
                mma16(of[0][2*p],   af[0][0], af[0][1], af[0][2], af[0][3], bf[0], bf[1]);
                mma16(of[0][2*p+1], af[0][0], af[0][1], af[0][2], af[0][3], bf[2], bf[3]);
                mma16(of[1][2*p],   af[1][0], af[1][1], af[1][2], af[1][3], bf[0], bf[1]);
                mma16(of[1][2*p+1], af[1][0], af[1][1], af[1][2], af[1][3], bf[2], bf[3]);
            }
        }
    }

    // epilogue
    const int b = bh >> 3, h = bh & 7;
    float inv[4];
#pragma unroll
    for (int r = 0; r < 4; r++) inv[r] = 1.f / lrow[r];
#pragma unroll
    for (int mi = 0; mi < 2; mi++) {
        size_t r0 = ((size_t)(b*SEQ + q0 + wm + 16*mi + g)) * EMBED + h*HDIM;
        size_t r1 = r0 + (size_t)8 * EMBED;
#pragma unroll
        for (int ni = 0; ni < 12; ni++) {
            *(__half2*)(g_atth + r0 + 8*ni + 2*q) =
                __floats2half2_rn(of[mi][ni][0]*inv[2*mi], of[mi][ni][1]*inv[2*mi]);
            *(__half2*)(g_atth + r1 + 8*ni + 2*q) =
                __floats2half2_rn(of[mi][ni][2]*inv[2*mi+1], of[mi][ni][3]*inv[2*mi+1]);
        }
    }
}

static const int FLASH_SMEM = (256*FQP + 2*64*FKP + 2*96*FVP) * 2;  // 107520

extern "C" void kernel_launch(void* const* d_in, const int* in_sizes, int n_in,
                              void* d_out, int out_size) {
    const float* x      = (const float*)d_in[0];
    const float* w_qkv  = (const float*)d_in[1];
    const float* w_proj = (const float*)d_in[2];
    float* out = (float*)d_out;

    static bool attr_set = false;
    if (!attr_set) {
        cudaFuncSetAttribute(flash_h, cudaFuncAttributeMaxDynamicSharedMemorySize,
                             FLASH_SMEM);
        cudaFuncSetAttribute(hgemm<0>, cudaFuncAttributeMaxDynamicSharedMemorySize,
                             HGEMM_SMEM);
        cudaFuncSetAttribute(hgemm<1>, cudaFuncAttributeMaxDynamicSharedMemorySize,
                             HGEMM_SMEM);
        attr_set = true;
    }

    __half *xh, *wqh, *wph;
    cudaGetSymbolAddress((void**)&xh,  g_xh);
    cudaGetSymbolAddress((void**)&wqh, g_wqkvh);
    cudaGetSymbolAddress((void**)&wph, g_wprojh);

    cvt_half<<<1024, 256>>>(x, xh, MTOT*EMBED/2);
    cvt_half<<<512, 256>>>(w_qkv, wqh, QKV_N*EMBED/2);
    cvt_half<<<256, 256>>>(w_proj, wph, EMBED*EMBED/2);

    hgemm<0><<<dim3(QKV_N/128, MTOT/128), 256, HGEMM_SMEM>>>(nullptr);
    flash_h<<<dim3(SEQ/256, BATCH*NHEAD), 256, FLASH_SMEM>>>();
    hgemm<1><<<dim3(EMBED/128, MTOT/128), 256, HGEMM_SMEM>>>(out);
}

// round 11
// speedup vs baseline: 1.0217x; 1.0217x over previous
#include <cuda_runtime.h>
#include <cuda_fp16.h>
#include <math.h>
#include <stdint.h>

#define BATCH 2
#define SEQ   4096
#define EMBED 768
#define NHEAD 8
#define HDIM  96
#define MTOT  (BATCH*SEQ)          // 8192
#define QKV_N (3*EMBED)            // 2304
#define C2EXP  0.14724446f         // 96^-0.5 * log2(e)

// ------------------------- device scratch (fp16) -------------------------
__device__ __align__(16) __half g_q[(size_t)BATCH*NHEAD*SEQ*HDIM];   // [B,H,N,D]
__device__ __align__(16) __half g_k[(size_t)BATCH*NHEAD*SEQ*HDIM];   // [B,H,N,D]
__device__ __align__(16) __half g_v[(size_t)BATCH*NHEAD*SEQ*HDIM];   // [B,H,D,N]
__device__ __align__(16) __half g_xh[(size_t)MTOT*EMBED];
__device__ __align__(16) __half g_wqkvh[(size_t)QKV_N*EMBED];
__device__ __align__(16) __half g_wprojh[(size_t)EMBED*EMBED];
__device__ __align__(16) __half g_atth[(size_t)MTOT*EMBED];

// ------------------------- helpers -------------------------
__device__ __forceinline__ void mma16(float* c, uint32_t a0, uint32_t a1,
                                      uint32_t a2, uint32_t a3,
                                      uint32_t b0, uint32_t b1) {
    asm volatile(
        "mma.sync.aligned.m16n8k16.row.col.f32.f16.f16.f32 "
        "{%0,%1,%2,%3}, {%4,%5,%6,%7}, {%8,%9}, {%0,%1,%2,%3};"
        : "+f"(c[0]), "+f"(c[1]), "+f"(c[2]), "+f"(c[3])
        : "r"(a0), "r"(a1), "r"(a2), "r"(a3), "r"(b0), "r"(b1));
}

#define LDSM4(R, addr) \
    asm volatile("ldmatrix.sync.aligned.m8n8.x4.shared.b16 {%0,%1,%2,%3}, [%4];" \
        : "=r"((R)[0]), "=r"((R)[1]), "=r"((R)[2]), "=r"((R)[3]) : "r"(addr))

__device__ __forceinline__ void cpasync16(uint32_t dst, const void* src) {
    asm volatile("cp.async.cg.shared.global [%0], [%1], 16;\n"
                 :: "r"(dst), "l"(src));
}

__device__ __forceinline__ uint32_t s2u(const void* p) {
    uint32_t a;
    asm("{ .reg .u64 t; cvta.to.shared.u64 t, %1; cvt.u32.u64 %0, t; }"
        : "=r"(a) : "l"(p));
    return a;
}

__device__ __forceinline__ uint32_t h2u(__half2 h) {
    return *(uint32_t*)&h;
}

// exp2 on a packed half2 pair (MUFU f16x2 path)
__device__ __forceinline__ uint32_t ex2h2(float a, float b) {
    uint32_t in = h2u(__floats2half2_rn(a, b)), out;
    asm("ex2.approx.f16x2 %0, %1;" : "=r"(out) : "r"(in));
    return out;
}

// ------------------------- fp32 -> fp16 convert -------------------------
__global__ void cvt_half(const float* __restrict__ s, __half* __restrict__ d, int n2) {
    for (int i = blockIdx.x * blockDim.x + threadIdx.x; i < n2;
         i += gridDim.x * blockDim.x) {
        float2 v = ((const float2*)s)[i];
        ((__half2*)d)[i] = __floats2half2_rn(v.x, v.y);
    }
}

// ---------------------------------------------------------------------------
// fp16 GEMM: C = A @ B^T, m16n8k16, f32 accum, ldmatrix fragment loads.
// 128x128 CTA tile, BK=64, cp.async 2-stage, 8 warps of 64x32, 2 CTAs/SM.
// ---------------------------------------------------------------------------
#define HGP 72
#define HST (128*HGP*2)
#define HGEMM_SMEM (4*HST)

template<int MODE>
__global__ __launch_bounds__(256, 2) void hgemm(float* __restrict__ Cout) {
    extern __shared__ char dynsm[];
    const uint32_t sb = s2u(dynsm);
    const int t = threadIdx.x, w = t >> 5, l = t & 31, g = l >> 2, q = l & 3;
    const int wm = (w >> 2) * 64, wn = (w & 3) * 32;
    const int m0 = blockIdx.y * 128, n0 = blockIdx.x * 128;
    const int K = EMBED;

    const int arow = (l & 7) + 8 * ((l >> 3) & 1);
    const int acol = 8 * (l >> 4);
    const int brow = (l & 7) + 8 * (l >> 4);
    const int bcol = 8 * ((l >> 3) & 1);

    const __half* A = (MODE == 0) ? g_xh : g_atth;
    const __half* B = (MODE == 0) ? g_wqkvh : g_wprojh;

    auto load_chunk = [&](int s, int kt) {
        uint32_t base = sb + s * (2 * HST);
#pragma unroll
        for (int j = 0; j < 8; j++) {
            int idx = t + j * 256;
            int tile = idx >> 10, rem = idx & 1023;
            int r = rem >> 3, cb = rem & 7;
            const __half* src = tile ? (B + (size_t)(n0 + r) * K)
                                     : (A + (size_t)(m0 + r) * K);
            cpasync16(base + tile * HST + (uint32_t)((r * HGP + cb * 8) * 2),
                      src + kt + cb * 8);
        }
        asm volatile("cp.async.commit_group;\n" ::);
    };

    float acc[4][4][4];
#pragma unroll
    for (int mi = 0; mi < 4; mi++)
#pragma unroll
        for (int ni = 0; ni < 4; ni++)
#pragma unroll
            for (int c = 0; c < 4; c++) acc[mi][ni][c] = 0.f;

    load_chunk(0, 0);

    for (int c = 0; c < 12; c++) {
        if (c + 1 < 12) {
            load_chunk((c + 1) & 1, (c + 1) * 64);
            asm volatile("cp.async.wait_group 1;\n" ::);
        } else {
            asm volatile("cp.async.wait_group 0;\n" ::);
        }
        __syncthreads();

        uint32_t as_s = sb + (c & 1) * (2 * HST);
        uint32_t bs_s = as_s + HST;

#pragma unroll
        for (int ks = 0; ks < 4; ks++) {
            uint32_t af[4][4], bf[2][4];
#pragma unroll
            for (int mi = 0; mi < 4; mi++)
                LDSM4(af[mi], as_s + (uint32_t)(((wm + 16*mi + arow) * HGP
                                                + 16*ks + acol) * 2));
#pragma unroll
            for (int p = 0; p < 2; p++)
                LDSM4(bf[p], bs_s + (uint32_t)(((wn + 16*p + brow) * HGP
                                                + 16*ks + bcol) * 2));
#pragma unroll
            for (int mi = 0; mi < 4; mi++)
#pragma unroll
                for (int ni = 0; ni < 4; ni++)
                    mma16(acc[mi][ni], af[mi][0], af[mi][1], af[mi][2], af[mi][3],
                          bf[ni >> 1][(ni & 1) * 2], bf[ni >> 1][(ni & 1) * 2 + 1]);
        }
        __syncthreads();
    }

#pragma unroll
    for (int mi = 0; mi < 4; mi++) {
        int gr0 = m0 + wm + 16 * mi + g;
        int gr1 = gr0 + 8;
#pragma unroll
        for (int ni = 0; ni < 4; ni++) {
            int colb = n0 + wn + 8 * ni;
            if (MODE == 0) {
                int which = colb / EMBED;
                int rem = colb - which * EMBED;
                int h = rem / HDIM;
                int d0 = rem - h * HDIM + 2 * q;
                int b0i = gr0 >> 12, n0i = gr0 & 4095;
                int b1i = gr1 >> 12, n1i = gr1 & 4095;
                if (which < 2) {
                    __half* dst = which ? g_k : g_q;
                    size_t i0 = (((size_t)(b0i * NHEAD + h)) * SEQ + n0i) * HDIM + d0;
                    size_t i1 = (((size_t)(b1i * NHEAD + h)) * SEQ + n1i) * HDIM + d0;
                    *(__half2*)(dst + i0) = __floats2half2_rn(acc[mi][ni][0], acc[mi][ni][1]);
                    *(__half2*)(dst + i1) = __floats2half2_rn(acc[mi][ni][2], acc[mi][ni][3]);
                } else {
                    size_t base0 = (((size_t)(b0i * NHEAD + h)) * HDIM + d0) * SEQ;
                    size_t base1 = (((size_t)(b1i * NHEAD + h)) * HDIM + d0) * SEQ;
                    g_v[base0 + n0i]       = __float2half(acc[mi][ni][0]);
                    g_v[base0 + SEQ + n0i] = __float2half(acc[mi][ni][1]);
                    g_v[base1 + n1i]       = __float2half(acc[mi][ni][2]);
                    g_v[base1 + SEQ + n1i] = __float2half(acc[mi][ni][3]);
                }
            } else {
                size_t i0 = (size_t)gr0 * EMBED + colb + 2 * q;
                size_t i1 = (size_t)gr1 * EMBED + colb + 2 * q;
                *(float2*)(Cout + i0) = make_float2(acc[mi][ni][0], acc[mi][ni][1]);
                *(float2*)(Cout + i1) = make_float2(acc[mi][ni][2], acc[mi][ni][3]);
            }
        }
    }
}

// ---------------------------------------------------------------------------
// Flash attention, fp16 m16n8k16, ldmatrix fragments, f16x2 exp, and the
// "P @ ones" row-sum trick: V tile carries 16 constant-one d-rows so the PV
// MMA accumulates the softmax denominator in an extra output column.
// Grid (SEQ/256, B*H), 256 threads, 1 CTA/SM. BM=256, BN=64, 8 warps x 32.
// ---------------------------------------------------------------------------
#define FQP 104
#define FKP 104
#define FVP 72
#define FVROWS 112   // 96 data d-rows + 16 ones-rows

__global__ __launch_bounds__(256, 1) void flash_h() {
    extern __shared__ char dynsm[];
    __half* Qs = (__half*)dynsm;                 // 256*FQP
    __half* Kb = Qs + 256*FQP;                   // 2 * 64*FKP
    __half* Vb = Kb + 2*64*FKP;                  // 2 * FVROWS*FVP

    const int t = threadIdx.x;
    const int w = t >> 5, l = t & 31, g = l >> 2, q = l & 3;
    const int wm = w * 32;
    const int bh = blockIdx.y;
    const int q0 = blockIdx.x * 256;

    const int arow = (l & 7) + 8 * ((l >> 3) & 1);
    const int acol = 8 * (l >> 4);
    const int brow = (l & 7) + 8 * (l >> 4);
    const int bcol = 8 * ((l >> 3) & 1);

    const __half* Qg = g_q + (size_t)bh * SEQ * HDIM;
    const __half* Kg = g_k + (size_t)bh * SEQ * HDIM;
    const __half* Vg = g_v + (size_t)bh * HDIM * SEQ;   // [D,N]

    const uint32_t qs_s = s2u(Qs);
    const uint32_t kb_s = s2u(Kb);
    const uint32_t vb_s = s2u(Vb);

#pragma unroll
    for (int j = 0; j < 12; j++) {
        int idx = t + j * 256;
        int r = idx / 12, cb = idx % 12;
        cpasync16(qs_s + (uint32_t)((r * FQP + cb * 8) * 2),
                  Qg + (size_t)(q0 + r) * HDIM + cb * 8);
    }
    asm volatile("cp.async.commit_group;\n" ::);

    // ones rows (96..111) of both V stages — never touched by loads
    for (int i = t; i < 2 * 16 * FVP; i += 256) {
        int s = i / (16 * FVP), rem = i % (16 * FVP);
        Vb[s * FVROWS * FVP + (96 + rem / FVP) * FVP + rem % FVP] = __float2half(1.f);
    }

    auto load_tile = [&](int s, int kt) {
#pragma unroll
        for (int j = 0; j < 3; j++) {
            int idx = t + j * 256;
            int r = idx / 12, cb = idx % 12;
            cpasync16(kb_s + (uint32_t)((s * 64 * FKP + r * FKP + cb * 8) * 2),
                      Kg + (size_t)(kt + r) * HDIM + cb * 8);
        }
#pragma unroll
        for (int j = 0; j < 3; j++) {
            int idx = t + j * 256;
            int r = idx >> 3, cb = idx & 7;
            cpasync16(vb_s + (uint32_t)((s * FVROWS * FVP + r * FVP + cb * 8) * 2),
                      Vg + (size_t)r * SEQ + kt + cb * 8);
        }
        asm volatile("cp.async.commit_group;\n" ::);
    };

    load_tile(0, 0);

    float of[2][14][4];          // 12 d-blocks + 2 ones-blocks (l in ni=12)
#pragma unroll
    for (int mi = 0; mi < 2; mi++)
#pragma unroll
        for (int ni = 0; ni < 14; ni++)
#pragma unroll
            for (int c = 0; c < 4; c++) of[mi][ni][c] = 0.f;
    float mrow[4] = {-INFINITY, -INFINITY, -INFINITY, -INFINITY};

    for (int it = 0; it < SEQ/64; it++) {
        asm volatile("cp.async.wait_group 0;\n" ::);
        __syncthreads();
        if (it + 1 < SEQ/64) load_tile((it + 1) & 1, (it + 1) * 64);

        const uint32_t kc_s = kb_s + (it & 1) * 64*FKP*2;
        const uint32_t vc_s = vb_s + (it & 1) * FVROWS*FVP*2;

        // ---- S = Q K^T ----
        float sacc[2][8][4];
#pragma unroll
        for (int mi = 0; mi < 2; mi++)
#pragma unroll
            for (int ni = 0; ni < 8; ni++)
#pragma unroll
                for (int c = 0; c < 4; c++) sacc[mi][ni][c] = 0.f;

#pragma unroll
        for (int kk = 0; kk < 6; kk++) {
            uint32_t qf[2][4];
#pragma unroll
            for (int mi = 0; mi < 2; mi++)
                LDSM4(qf[mi], qs_s + (uint32_t)(((wm + 16*mi + arow) * FQP
                                                 + 16*kk + acol) * 2));
#pragma unroll
            for (int p = 0; p < 4; p++) {
                uint32_t bf[4];
                LDSM4(bf, kc_s + (uint32_t)(((16*p + brow) * FKP
                                             + 16*kk + bcol) * 2));
                mma16(sacc[0][2*p],   qf[0][0], qf[0][1], qf[0][2], qf[0][3], bf[0], bf[1]);
                mma16(sacc[0][2*p+1], qf[0][0], qf[0][1], qf[0][2], qf[0][3], bf[2], bf[3]);
                mma16(sacc[1][2*p],   qf[1][0], qf[1][1], qf[1][2], qf[1][3], bf[0], bf[1]);
                mma16(sacc[1][2*p+1], qf[1][0], qf[1][1], qf[1][2], qf[1][3], bf[2], bf[3]);
            }
        }

        // ---- softmax: max + f16x2 exp (sums come from the PV ones-column) ----
        float tm[4] = {-INFINITY, -INFINITY, -INFINITY, -INFINITY};
#pragma unroll
        for (int mi = 0; mi < 2; mi++)
#pragma unroll
            for (int ni = 0; ni < 8; ni++) {
                tm[2*mi]   = fmaxf(tm[2*mi],   fmaxf(sacc[mi][ni][0], sacc[mi][ni][1]));
                tm[2*mi+1] = fmaxf(tm[2*mi+1], fmaxf(sacc[mi][ni][2], sacc[mi][ni][3]));
            }
        float sc[4], base[4];
#pragma unroll
        for (int r = 0; r < 4; r++) {
            tm[r] = fmaxf(tm[r], __shfl_xor_sync(0xffffffffu, tm[r], 1));
            tm[r] = fmaxf(tm[r], __shfl_xor_sync(0xffffffffu, tm[r], 2));
            float mn = fmaxf(mrow[r], tm[r]);
            sc[r]   = exp2f((mrow[r] - mn) * C2EXP);
            base[r] = mn * C2EXP;
            mrow[r] = mn;
        }
        uint32_t p16[2][8][2];
#pragma unroll
        for (int mi = 0; mi < 2; mi++)
#pragma unroll
            for (int ni = 0; ni < 8; ni++) {
                p16[mi][ni][0] = ex2h2(fmaf(sacc[mi][ni][0], C2EXP, -base[2*mi]),
                                       fmaf(sacc[mi][ni][1], C2EXP, -base[2*mi]));
                p16[mi][ni][1] = ex2h2(fmaf(sacc[mi][ni][2], C2EXP, -base[2*mi+1]),
                                       fmaf(sacc[mi][ni][3], C2EXP, -base[2*mi+1]));
            }
        bool any_scale = !__all_sync(0xffffffffu,
            (sc[0] == 1.f) & (sc[1] == 1.f) & (sc[2] == 1.f) & (sc[3] == 1.f));
        if (any_scale) {
#pragma unroll
            for (int mi = 0; mi < 2; mi++)
#pragma unroll
                for (int ni = 0; ni < 14; ni++) {   // includes the l columns
                    of[mi][ni][0] *= sc[2*mi];   of[mi][ni][1] *= sc[2*mi];
                    of[mi][ni][2] *= sc[2*mi+1]; of[mi][ni][3] *= sc[2*mi+1];
                }
        }

        // ---- O += P @ [V | 1] ----
#pragma unroll
        for (int kk2 = 0; kk2 < 4; kk2++) {
            uint32_t af[2][4];
#pragma unroll
            for (int mi = 0; mi < 2; mi++) {
                af[mi][0] = p16[mi][2*kk2][0];
                af[mi][1] = p16[mi][2*kk2][1];
                af[mi][2] = p16[mi][2*kk2+1][0];
                af[mi][3] = p16[mi][2*kk2+1][1];
            }
#pragma unroll
            for (int p = 0; p < 7; p++) {
                uint32_t bf[4];
                LDSM4(bf, vc_s + (uint32_t)(((16*p + brow) * FVP
                                             + 16*kk2 + bcol) * 2));
                mma16(of[0][2*p],   af[0][0], af[0][1], af[0][2], af[0][3], bf[0], bf[1]);
                mma16(of[0][2*p+1], af[0][0], af[0][1], af[0][2], af[0][3], bf[2], bf[3]);
                mma16(of[1][2*p],   af[1][0], af[1][1], af[1][2], af[1][3], bf[0], bf[1]);
                mma16(of[1][2*p+1], af[1][0], af[1][1], af[1][2], af[1][3], bf[2], bf[3]);
            }
        }
    }

    // epilogue: l comes from the ones-column accumulators
    const int b = bh >> 3, h = bh & 7;
    float inv[4];
    inv[0] = 1.f / of[0][12][0];
    inv[1] = 1.f / of[0][12][2];
    inv[2] = 1.f / of[1][12][0];
    inv[3] = 1.f / of[1][12][2];
#pragma unroll
    for (int mi = 0; mi < 2; mi++) {
        size_t r0 = ((size_t)(b*SEQ + q0 + wm + 16*mi + g)) * EMBED + h*HDIM;
        size_t r1 = r0 + (size_t)8 * EMBED;
#pragma unroll
        for (int ni = 0; ni < 12; ni++) {
            *(__half2*)(g_atth + r0 + 8*ni + 2*q) =
                __floats2half2_rn(of[mi][ni][0]*inv[2*mi], of[mi][ni][1]*inv[2*mi]);
            *(__half2*)(g_atth + r1 + 8*ni + 2*q) =
                __floats2half2_rn(of[mi][ni][2]*inv[2*mi+1], of[mi][ni][3]*inv[2*mi+1]);
        }
    }
}

static const int FLASH_SMEM = (256*FQP + 2*64*FKP + 2*FVROWS*FVP) * 2;  // 112128

extern "C" void kernel_launch(void* const* d_in, const int* in_sizes, int n_in,
                              void* d_out, int out_size) {
    const float* x      = (const float*)d_in[0];
    const float* w_qkv  = (const float*)d_in[1];
    const float* w_proj = (const float*)d_in[2];
    float* out = (float*)d_out;

    static bool attr_set = false;
    if (!attr_set) {
        cudaFuncSetAttribute(flash_h, cudaFuncAttributeMaxDynamicSharedMemorySize,
                             FLASH_SMEM);
        cudaFuncSetAttribute(hgemm<0>, cudaFuncAttributeMaxDynamicSharedMemorySize,
                             HGEMM_SMEM);
        cudaFuncSetAttribute(hgemm<1>, cudaFuncAttributeMaxDynamicSharedMemorySize,
                             HGEMM_SMEM);
        attr_set = true;
    }

    __half *xh, *wqh, *wph;
    cudaGetSymbolAddress((void**)&xh,  g_xh);
    cudaGetSymbolAddress((void**)&wqh, g_wqkvh);
    cudaGetSymbolAddress((void**)&wph, g_wprojh);

    cvt_half<<<1024, 256>>>(x, xh, MTOT*EMBED/2);
    cvt_half<<<512, 256>>>(w_qkv, wqh, QKV_N*EMBED/2);
    cvt_half<<<256, 256>>>(w_proj, wph, EMBED*EMBED/2);

    hgemm<0><<<dim3(QKV_N/128, MTOT/128), 256, HGEMM_SMEM>>>(nullptr);
    flash_h<<<dim3(SEQ/256, BATCH*NHEAD), 256, FLASH_SMEM>>>();
    hgemm<1><<<dim3(EMBED/128, MTOT/128), 256, HGEMM_SMEM>>>(out);
}

// round 12
// speedup vs baseline: 1.0384x; 1.0164x over previous
#include <cuda_runtime.h>
#include <cuda_fp16.h>
#include <math.h>
#include <stdint.h>

#define BATCH 2
#define SEQ   4096
#define EMBED 768
#define NHEAD 8
#define HDIM  96
#define MTOT  (BATCH*SEQ)          // 8192
#define QKV_N (3*EMBED)            // 2304
#define C2EXP  0.14724446f         // 96^-0.5 * log2(e)

// ------------------------- device scratch (fp16) -------------------------
__device__ __align__(16) __half g_q[(size_t)BATCH*NHEAD*SEQ*HDIM];   // [B,H,N,D]
__device__ __align__(16) __half g_k[(size_t)BATCH*NHEAD*SEQ*HDIM];   // [B,H,N,D]
__device__ __align__(16) __half g_v[(size_t)BATCH*NHEAD*SEQ*HDIM];   // [B,H,D,N]
__device__ __align__(16) __half g_xh[(size_t)MTOT*EMBED];
__device__ __align__(16) __half g_wqkvh[(size_t)QKV_N*EMBED];
__device__ __align__(16) __half g_wprojh[(size_t)EMBED*EMBED];
__device__ __align__(16) __half g_atth[(size_t)MTOT*EMBED];

// ------------------------- helpers -------------------------
__device__ __forceinline__ void mma16(float* c, uint32_t a0, uint32_t a1,
                                      uint32_t a2, uint32_t a3,
                                      uint32_t b0, uint32_t b1) {
    asm volatile(
        "mma.sync.aligned.m16n8k16.row.col.f32.f16.f16.f32 "
        "{%0,%1,%2,%3}, {%4,%5,%6,%7}, {%8,%9}, {%0,%1,%2,%3};"
        : "+f"(c[0]), "+f"(c[1]), "+f"(c[2]), "+f"(c[3])
        : "r"(a0), "r"(a1), "r"(a2), "r"(a3), "r"(b0), "r"(b1));
}

#define LDSM4(R, addr) \
    asm volatile("ldmatrix.sync.aligned.m8n8.x4.shared.b16 {%0,%1,%2,%3}, [%4];" \
        : "=r"((R)[0]), "=r"((R)[1]), "=r"((R)[2]), "=r"((R)[3]) : "r"(addr))

__device__ __forceinline__ void cpasync16(uint32_t dst, const void* src) {
    asm volatile("cp.async.cg.shared.global [%0], [%1], 16;\n"
                 :: "r"(dst), "l"(src));
}

__device__ __forceinline__ uint32_t s2u(const void* p) {
    uint32_t a;
    asm("{ .reg .u64 t; cvta.to.shared.u64 t, %1; cvt.u32.u64 %0, t; }"
        : "=r"(a) : "l"(p));
    return a;
}

__device__ __forceinline__ uint32_t h2u(__half2 h) {
    return *(uint32_t*)&h;
}

// exp2 on a packed half2 pair (MUFU f16x2 path); result feeds PV A-frag directly
__device__ __forceinline__ uint32_t ex2h2(float a, float b) {
    uint32_t in = h2u(__floats2half2_rn(a, b)), out;
    asm("ex2.approx.f16x2 %0, %1;" : "=r"(out) : "r"(in));
    return out;
}

// half2 -> two floats (for the fp32 row-sum)
__device__ __forceinline__ float2 h2f2(uint32_t u) {
    __half2 h = *(__half2*)&u;
    return __half22float2(h);
}

// ------------------------- fused fp32 -> fp16 convert -------------------------
#define N2_X  (MTOT*EMBED/2)
#define N2_WQ (QKV_N*EMBED/2)
#define N2_WP (EMBED*EMBED/2)

__global__ void cvt_all(const float* __restrict__ x,
                        const float* __restrict__ wq,
                        const float* __restrict__ wp) {
    const int total = N2_X + N2_WQ + N2_WP;
    for (int i = blockIdx.x * blockDim.x + threadIdx.x; i < total;
         i += gridDim.x * blockDim.x) {
        const float2* s;
        __half2* d;
        int j = i;
        if (j < N2_X) { s = (const float2*)x; d = (__half2*)g_xh; }
        else if ((j -= N2_X) < N2_WQ) { s = (const float2*)wq; d = (__half2*)g_wqkvh; }
        else { j -= N2_WQ; s = (const float2*)wp; d = (__half2*)g_wprojh; }
        float2 v = s[j];
        d[j] = __floats2half2_rn(v.x, v.y);
    }
}

// ---------------------------------------------------------------------------
// fp16 GEMM: C = A @ B^T, m16n8k16, f32 accum, ldmatrix fragment loads.
// 128x128 CTA tile, BK=64, cp.async 2-stage, 8 warps of 64x32, 2 CTAs/SM.
// ---------------------------------------------------------------------------
#define HGP 72
#define HST (128*HGP*2)
#define HGEMM_SMEM (4*HST)

template<int MODE>
__global__ __launch_bounds__(256, 2) void hgemm(float* __restrict__ Cout) {
    extern __shared__ char dynsm[];
    const uint32_t sb = s2u(dynsm);
    const int t = threadIdx.x, w = t >> 5, l = t & 31, g = l >> 2, q = l & 3;
    const int wm = (w >> 2) * 64, wn = (w & 3) * 32;
    const int m0 = blockIdx.y * 128, n0 = blockIdx.x * 128;
    const int K = EMBED;

    const int arow = (l & 7) + 8 * ((l >> 3) & 1);
    const int acol = 8 * (l >> 4);
    const int brow = (l & 7) + 8 * (l >> 4);
    const int bcol = 8 * ((l >> 3) & 1);

    const __half* A = (MODE == 0) ? g_xh : g_atth;
    const __half* B = (MODE == 0) ? g_wqkvh : g_wprojh;

    auto load_chunk = [&](int s, int kt) {
        uint32_t base = sb + s * (2 * HST);
#pragma unroll
        for (int j = 0; j < 8; j++) {
            int idx = t + j * 256;
            int tile = idx >> 10, rem = idx & 1023;
            int r = rem >> 3, cb = rem & 7;
            const __half* src = tile ? (B + (size_t)(n0 + r) * K)
                                     : (A + (size_t)(m0 + r) * K);
            cpasync16(base + tile * HST + (uint32_t)((r * HGP + cb * 8) * 2),
                      src + kt + cb * 8);
        }
        asm volatile("cp.async.commit_group;\n" ::);
    };

    float acc[4][4][4];
#pragma unroll
    for (int mi = 0; mi < 4; mi++)
#pragma unroll
        for (int ni = 0; ni < 4; ni++)
#pragma unroll
            for (int c = 0; c < 4; c++) acc[mi][ni][c] = 0.f;

    load_chunk(0, 0);

    for (int c = 0; c < 12; c++) {
        if (c + 1 < 12) {
            load_chunk((c + 1) & 1, (c + 1) * 64);
            asm volatile("cp.async.wait_group 1;\n" ::);
        } else {
            asm volatile("cp.async.wait_group 0;\n" ::);
        }
        __syncthreads();

        uint32_t as_s = sb + (c & 1) * (2 * HST);
        uint32_t bs_s = as_s + HST;

#pragma unroll
        for (int ks = 0; ks < 4; ks++) {
            uint32_t af[4][4], bf[2][4];
#pragma unroll
            for (int mi = 0; mi < 4; mi++)
                LDSM4(af[mi], as_s + (uint32_t)(((wm + 16*mi + arow) * HGP
                                                + 16*ks + acol) * 2));
#pragma unroll
            for (int p = 0; p < 2; p++)
                LDSM4(bf[p], bs_s + (uint32_t)(((wn + 16*p + brow) * HGP
                                                + 16*ks + bcol) * 2));
#pragma unroll
            for (int mi = 0; mi < 4; mi++)
#pragma unroll
                for (int ni = 0; ni < 4; ni++)
                    mma16(acc[mi][ni], af[mi][0], af[mi][1], af[mi][2], af[mi][3],
                          bf[ni >> 1][(ni & 1) * 2], bf[ni >> 1][(ni & 1) * 2 + 1]);
        }
        __syncthreads();
    }

#pragma unroll
    for (int mi = 0; mi < 4; mi++) {
        int gr0 = m0 + wm + 16 * mi + g;
        int gr1 = gr0 + 8;
#pragma unroll
        for (int ni = 0; ni < 4; ni++) {
            int colb = n0 + wn + 8 * ni;
            if (MODE == 0) {
                int which = colb / EMBED;
                int rem = colb - which * EMBED;
                int h = rem / HDIM;
                int d0 = rem - h * HDIM + 2 * q;
                int b0i = gr0 >> 12, n0i = gr0 & 4095;
                int b1i = gr1 >> 12, n1i = gr1 & 4095;
                if (which < 2) {
                    __half* dst = which ? g_k : g_q;
                    size_t i0 = (((size_t)(b0i * NHEAD + h)) * SEQ + n0i) * HDIM + d0;
                    size_t i1 = (((size_t)(b1i * NHEAD + h)) * SEQ + n1i) * HDIM + d0;
                    *(__half2*)(dst + i0) = __floats2half2_rn(acc[mi][ni][0], acc[mi][ni][1]);
                    *(__half2*)(dst + i1) = __floats2half2_rn(acc[mi][ni][2], acc[mi][ni][3]);
                } else {
                    size_t base0 = (((size_t)(b0i * NHEAD + h)) * HDIM + d0) * SEQ;
                    size_t base1 = (((size_t)(b1i * NHEAD + h)) * HDIM + d0) * SEQ;
                    g_v[base0 + n0i]       = __float2half(acc[mi][ni][0]);
                    g_v[base0 + SEQ + n0i] = __float2half(acc[mi][ni][1]);
                    g_v[base1 + n1i]       = __float2half(acc[mi][ni][2]);
                    g_v[base1 + SEQ + n1i] = __float2half(acc[mi][ni][3]);
                }
            } else {
                size_t i0 = (size_t)gr0 * EMBED + colb + 2 * q;
                size_t i1 = (size_t)gr1 * EMBED + colb + 2 * q;
                *(float2*)(Cout + i0) = make_float2(acc[mi][ni][0], acc[mi][ni][1]);
                *(float2*)(Cout + i1) = make_float2(acc[mi][ni][2], acc[mi][ni][3]);
            }
        }
    }
}

// ---------------------------------------------------------------------------
// Flash attention, fp16 m16n8k16, ldmatrix fragments, f16x2 exp, fp32 shfl
// row-sums (no ones-columns: PV kept at the 96-row minimum MMA work).
// Grid (SEQ/256, B*H), 256 threads, 1 CTA/SM. BM=256, BN=64, 8 warps x 32.
// ---------------------------------------------------------------------------
#define FQP 104
#define FKP 104
#define FVP 72

__global__ __launch_bounds__(256, 1) void flash_h() {
    extern __shared__ char dynsm[];
    __half* Qs = (__half*)dynsm;                 // 256*FQP
    __half* Kb = Qs + 256*FQP;                   // 2 * 64*FKP
    __half* Vb = Kb + 2*64*FKP;                  // 2 * 96*FVP

    const int t = threadIdx.x;
    const int w = t >> 5, l = t & 31, g = l >> 2, q = l & 3;
    const int wm = w * 32;
    const int bh = blockIdx.y;
    const int q0 = blockIdx.x * 256;

    const int arow = (l & 7) + 8 * ((l >> 3) & 1);
    const int acol = 8 * (l >> 4);
    const int brow = (l & 7) + 8 * (l >> 4);
    const int bcol = 8 * ((l >> 3) & 1);

    const __half* Qg = g_q + (size_t)bh * SEQ * HDIM;
    const __half* Kg = g_k + (size_t)bh * SEQ * HDIM;
    const __half* Vg = g_v + (size_t)bh * HDIM * SEQ;   // [D,N]

    const uint32_t qs_s = s2u(Qs);
    const uint32_t kb_s = s2u(Kb);
    const uint32_t vb_s = s2u(Vb);

#pragma unroll
    for (int j = 0; j < 12; j++) {
        int idx = t + j * 256;
        int r = idx / 12, cb = idx % 12;
        cpasync16(qs_s + (uint32_t)((r * FQP + cb * 8) * 2),
                  Qg + (size_t)(q0 + r) * HDIM + cb * 8);
    }
    asm volatile("cp.async.commit_group;\n" ::);

    auto load_tile = [&](int s, int kt) {
#pragma unroll
        for (int j = 0; j < 3; j++) {
            int idx = t + j * 256;
            int r = idx / 12, cb = idx % 12;
            cpasync16(kb_s + (uint32_t)((s * 64 * FKP + r * FKP + cb * 8) * 2),
                      Kg + (size_t)(kt + r) * HDIM + cb * 8);
        }
#pragma unroll
        for (int j = 0; j < 3; j++) {
            int idx = t + j * 256;
            int r = idx >> 3, cb = idx & 7;
            cpasync16(vb_s + (uint32_t)((s * 96 * FVP + r * FVP + cb * 8) * 2),
                      Vg + (size_t)r * SEQ + kt + cb * 8);
        }
        asm volatile("cp.async.commit_group;\n" ::);
    };

    load_tile(0, 0);

    float of[2][12][4];
#pragma unroll
    for (int mi = 0; mi < 2; mi++)
#pragma unroll
        for (int ni = 0; ni < 12; ni++)
#pragma unroll
            for (int c = 0; c < 4; c++) of[mi][ni][c] = 0.f;
    float mrow[4] = {-INFINITY, -INFINITY, -INFINITY, -INFINITY};
    float lrow[4] = {0.f, 0.f, 0.f, 0.f};

    for (int it = 0; it < SEQ/64; it++) {
        asm volatile("cp.async.wait_group 0;\n" ::);
        __syncthreads();
        if (it + 1 < SEQ/64) load_tile((it + 1) & 1, (it + 1) * 64);

        const uint32_t kc_s = kb_s + (it & 1) * 64*FKP*2;
        const uint32_t vc_s = vb_s + (it & 1) * 96*FVP*2;

        // ---- S = Q K^T ----
        float sacc[2][8][4];
#pragma unroll
        for (int mi = 0; mi < 2; mi++)
#pragma unroll
            for (int ni = 0; ni < 8; ni++)
#pragma unroll
                for (int c = 0; c < 4; c++) sacc[mi][ni][c] = 0.f;

#pragma unroll
        for (int kk = 0; kk < 6; kk++) {
            uint32_t qf[2][4];
#pragma unroll
            for (int mi = 0; mi < 2; mi++)
                LDSM4(qf[mi], qs_s + (uint32_t)(((wm + 16*mi + arow) * FQP
                                                 + 16*kk + acol) * 2));
#pragma unroll
            for (int p = 0; p < 4; p++) {
                uint32_t bf[4];
                LDSM4(bf, kc_s + (uint32_t)(((16*p + brow) * FKP
                                             + 16*kk + bcol) * 2));
                mma16(sacc[0][2*p],   qf[0][0], qf[0][1], qf[0][2], qf[0][3], bf[0], bf[1]);
                mma16(sacc[0][2*p+1], qf[0][0], qf[0][1], qf[0][2], qf[0][3], bf[2], bf[3]);
                mma16(sacc[1][2*p],   qf[1][0], qf[1][1], qf[1][2], qf[1][3], bf[0], bf[1]);
                mma16(sacc[1][2*p+1], qf[1][0], qf[1][1], qf[1][2], qf[1][3], bf[2], bf[3]);
            }
        }

        // ---- softmax: max + f16x2 exp + fp32 shfl sums ----
        float tm[4] = {-INFINITY, -INFINITY, -INFINITY, -INFINITY};
#pragma unroll
        for (int mi = 0; mi < 2; mi++)
#pragma unroll
            for (int ni = 0; ni < 8; ni++) {
                tm[2*mi]   = fmaxf(tm[2*mi],   fmaxf(sacc[mi][ni][0], sacc[mi][ni][1]));
                tm[2*mi+1] = fmaxf(tm[2*mi+1], fmaxf(sacc[mi][ni][2], sacc[mi][ni][3]));
            }
        float sc[4], base[4], ssum[4];
#pragma unroll
        for (int r = 0; r < 4; r++) {
            tm[r] = fmaxf(tm[r], __shfl_xor_sync(0xffffffffu, tm[r], 1));
            tm[r] = fmaxf(tm[r], __shfl_xor_sync(0xffffffffu, tm[r], 2));
            float mn = fmaxf(mrow[r], tm[r]);
            sc[r]   = exp2f((mrow[r] - mn) * C2EXP);
            base[r] = mn * C2EXP;
            mrow[r] = mn;
            ssum[r] = 0.f;
        }
        uint32_t p16[2][8][2];
#pragma unroll
        for (int mi = 0; mi < 2; mi++)
#pragma unroll
            for (int ni = 0; ni < 8; ni++) {
                p16[mi][ni][0] = ex2h2(fmaf(sacc[mi][ni][0], C2EXP, -base[2*mi]),
                                       fmaf(sacc[mi][ni][1], C2EXP, -base[2*mi]));
                p16[mi][ni][1] = ex2h2(fmaf(sacc[mi][ni][2], C2EXP, -base[2*mi+1]),
                                       fmaf(sacc[mi][ni][3], C2EXP, -base[2*mi+1]));
                float2 f0 = h2f2(p16[mi][ni][0]);
                float2 f1 = h2f2(p16[mi][ni][1]);
                ssum[2*mi]   += f0.x + f0.y;
                ssum[2*mi+1] += f1.x + f1.y;
            }
#pragma unroll
        for (int r = 0; r < 4; r++) {
            ssum[r] += __shfl_xor_sync(0xffffffffu, ssum[r], 1);
            ssum[r] += __shfl_xor_sync(0xffffffffu, ssum[r], 2);
            lrow[r] = lrow[r] * sc[r] + ssum[r];
        }
        bool any_scale = !__all_sync(0xffffffffu,
            (sc[0] == 1.f) & (sc[1] == 1.f) & (sc[2] == 1.f) & (sc[3] == 1.f));
        if (any_scale) {
#pragma unroll
            for (int mi = 0; mi < 2; mi++)
#pragma unroll
                for (int ni = 0; ni < 12; ni++) {
                    of[mi][ni][0] *= sc[2*mi];   of[mi][ni][1] *= sc[2*mi];
                    of[mi][ni][2] *= sc[2*mi+1]; of[mi][ni][3] *= sc[2*mi+1];
                }
        }

        // ---- O += P @ V ----
#pragma unroll
        for (int kk2 = 0; kk2 < 4; kk2++) {
            uint32_t af[2][4];
#pragma unroll
            for (int mi = 0; mi < 2; mi++) {
                af[mi][0] = p16[mi][2*kk2][0];
                af[mi][1] = p16[mi][2*kk2][1];
                af[mi][2] = p16[mi][2*kk2+1][0];
                af[mi][3] = p16[mi][2*kk2+1][1];
            }
#pragma unroll
            for (int p = 0; p < 6; p++) {
                uint32_t bf[4];
                LDSM4(bf, vc_s + (uint32_t)(((16*p + brow) * FVP
                                             + 16*kk2 + bcol) * 2));
                mma16(of[0][2*p],   af[0][0], af[0][1], af[0][2], af[0][3], bf[0], bf[1]);
                mma16(of[0][2*p+1], af[0][0], af[0][1], af[0][2], af[0][3], bf[2], bf[3]);
                mma16(of[1][2*p],   af[1][0], af[1][1], af[1][2], af[1][3], bf[0], bf[1]);
                mma16(of[1][2*p+1], af[1][0], af[1][1], af[1][2], af[1][3], bf[2], bf[3]);
            }
        }
    }

    // epilogue
    const int b = bh >> 3, h = bh & 7;
    float inv[4];
#pragma unroll
    for (int r = 0; r < 4; r++) inv[r] = 1.f / lrow[r];
#pragma unroll
    for (int mi = 0; mi < 2; mi++) {
        size_t r0 = ((size_t)(b*SEQ + q0 + wm + 16*mi + g)) * EMBED + h*HDIM;
        size_t r1 = r0 + (size_t)8 * EMBED;
#pragma unroll
        for (int ni = 0; ni < 12; ni++) {
            *(__half2*)(g_atth + r0 + 8*ni + 2*q) =
                __floats2half2_rn(of[mi][ni][0]*inv[2*mi], of[mi][ni][1]*inv[2*mi]);
            *(__half2*)(g_atth + r1 + 8*ni + 2*q) =
                __floats2half2_rn(of[mi][ni][2]*inv[2*mi+1], of[mi][ni][3]*inv[2*mi+1]);
        }
    }
}

static const int FLASH_SMEM = (256*FQP + 2*64*FKP + 2*96*FVP) * 2;  // 107520

extern "C" void kernel_launch(void* const* d_in, const int* in_sizes, int n_in,
                              void* d_out, int out_size) {
    const float* x      = (const float*)d_in[0];
    const float* w_qkv  = (const float*)d_in[1];
    const float* w_proj = (const float*)d_in[2];
    float* out = (float*)d_out;

    static bool attr_set = false;
    if (!attr_set) {
        cudaFuncSetAttribute(flash_h, cudaFuncAttributeMaxDynamicSharedMemorySize,
                             FLASH_SMEM);
        cudaFuncSetAttribute(hgemm<0>, cudaFuncAttributeMaxDynamicSharedMemorySize,
                             HGEMM_SMEM);
        cudaFuncSetAttribute(hgemm<1>, cudaFuncAttributeMaxDynamicSharedMemorySize,
                             HGEMM_SMEM);
        attr_set = true;
    }

    cvt_all<<<2048, 256>>>(x, w_qkv, w_proj);
    hgemm<0><<<dim3(QKV_N/128, MTOT/128), 256, HGEMM_SMEM>>>(nullptr);
    flash_h<<<dim3(SEQ/256, BATCH*NHEAD), 256, FLASH_SMEM>>>();
    hgemm<1><<<dim3(EMBED/128, MTOT/128), 256, HGEMM_SMEM>>>(out);
}